// round 1
// baseline (speedup 1.0000x reference)
#include <cuda_runtime.h>
#include <cstdint>

// Problem constants
#define NN   256    // chain count / sequence length
#define DDIM 16     // bond dimension
#define FF   2      // feature count
#define BSZ  512    // batch size
#define TPB  128    // threads per chain-block (samples per quarter)
#define NQ   4      // sample quarters
#define TILE 512    // floats per (n,i) tile = 16*16*2
#define FSTR 264    // smem stride between f=0 and f=1 matrices (16*16 + pad)

// Scratch (device globals; no dynamic allocation allowed)
__device__ float        g_terms[NN * BSZ];   // per-chain per-sample log-softmax terms (row 0 unused)
__device__ unsigned int g_fbits[BSZ * 8];    // packed data bits: bit i of sample b

// ---------------------------------------------------------------------------
// Pack data (int64, values in {0,1}) into per-sample bitmasks.
// One thread per 32-bit word: 512 samples * 8 words = 4096 threads.
// ---------------------------------------------------------------------------
__global__ void pack_kernel(const long long* __restrict__ data) {
    int idx = blockIdx.x * blockDim.x + threadIdx.x;   // 0..4095
    int b = idx >> 3;
    int w = idx & 7;
    const long long* p = data + (size_t)b * NN + w * 32;
    unsigned int m = 0;
#pragma unroll
    for (int j = 0; j < 32; ++j)
        m |= ((unsigned int)(p[j] & 1LL)) << j;
    g_fbits[b * 8 + w] = m;
}

// ---------------------------------------------------------------------------
// Chain kernel: block = (chain n, sample quarter q). Each thread owns one
// sample's 16-vector in registers and walks the chain sequentially.
// Matrix tile for step i staged in smem transposed to [f][r][k] so the inner
// loop is pure broadcast-LDS + FFMA.
// ---------------------------------------------------------------------------
__global__ __launch_bounds__(TPB)
void chain_kernel(const float* __restrict__ T) {
    // ---- snake work mapping over residue classes mod 148 (classic LUT is
    //      bid%148 -> SM), longest chains first ----
    int bx = blockIdx.x;          // 0..1019
    int g  = bx / 148;
    int c  = bx % 148;
    int w  = g * 148 + ((g & 1) ? (147 - c) : c);
    int n  = 255 - (w >> 2);      // chain id 255..1
    int q  = w & 3;               // sample quarter

    int tid = threadIdx.x;
    int b   = q * TPB + tid;      // sample id

    const float* Tn = T + (size_t)n * (NN * TILE);   // tensors[n, :, :, :, :]

    // smem: double buffer x {f=0 matrix, f=1 matrix}, FSTR-padded
    __shared__ float sm[2][2 * FSTR];

    // per-sample packed f bits
    unsigned int fb[8];
#pragma unroll
    for (int ww = 0; ww < 8; ++ww) fb[ww] = g_fbits[b * 8 + ww];

    // ---- init lv from tensors[n,0,0,r,f0] + e0 ----
    int f0 = fb[0] & 1;
    float lv[16];
#pragma unroll
    for (int r = 0; r < 16; ++r)
        lv[r] = __ldg(Tn + r * 2 + f0) + (r == 0 ? 1.0f : 0.0f);

    // ---- prefetch tile i=1 (each thread carries one float4 = elements 4t..4t+3) ----
    float4 pre = make_float4(0.f, 0.f, 0.f, 0.f);
    if (n >= 2)
        pre = __ldg(reinterpret_cast<const float4*>(Tn + TILE) + tid);

    // staging coords: element 4t -> r = t/8, k0 = (t%8)*2, pairs over f
    int srr = tid >> 3;
    int skk = (tid & 7) * 2;
    int soff = srr * 16 + skk;

    int p = 0;
    for (int i = 1; i < n; ++i) {
        // stage tile i into buffer p, transposed to [f][r][k]
        float* s0 = &sm[p][soff];
        float* s1 = &sm[p][FSTR + soff];
        s0[0] = pre.x;  s0[1] = pre.z;   // f = 0: (r,k0), (r,k0+1)
        s1[0] = pre.y;  s1[1] = pre.w;   // f = 1
        __syncthreads();

        // prefetch next tile while computing this one
        if (i + 1 < n)
            pre = __ldg(reinterpret_cast<const float4*>(Tn + (size_t)(i + 1) * TILE) + tid);

        int f = (fb[i >> 5] >> (i & 31)) & 1;
        const float* M = &sm[p][f * FSTR];

        float acc[16];
#pragma unroll
        for (int k = 0; k < 16; ++k) acc[k] = lv[k];   // identity part of (I + T)

#pragma unroll
        for (int r = 0; r < 16; ++r) {
            float a = lv[r];
            float4 v0 = *reinterpret_cast<const float4*>(M + r * 16);
            float4 v1 = *reinterpret_cast<const float4*>(M + r * 16 + 4);
            float4 v2 = *reinterpret_cast<const float4*>(M + r * 16 + 8);
            float4 v3 = *reinterpret_cast<const float4*>(M + r * 16 + 12);
            acc[0]  = fmaf(a, v0.x, acc[0]);
            acc[1]  = fmaf(a, v0.y, acc[1]);
            acc[2]  = fmaf(a, v0.z, acc[2]);
            acc[3]  = fmaf(a, v0.w, acc[3]);
            acc[4]  = fmaf(a, v1.x, acc[4]);
            acc[5]  = fmaf(a, v1.y, acc[5]);
            acc[6]  = fmaf(a, v1.z, acc[6]);
            acc[7]  = fmaf(a, v1.w, acc[7]);
            acc[8]  = fmaf(a, v2.x, acc[8]);
            acc[9]  = fmaf(a, v2.y, acc[9]);
            acc[10] = fmaf(a, v2.z, acc[10]);
            acc[11] = fmaf(a, v2.w, acc[11]);
            acc[12] = fmaf(a, v3.x, acc[12]);
            acc[13] = fmaf(a, v3.y, acc[13]);
            acc[14] = fmaf(a, v3.z, acc[14]);
            acc[15] = fmaf(a, v3.w, acc[15]);
        }
#pragma unroll
        for (int k = 0; k < 16; ++k) lv[k] = acc[k];

        p ^= 1;
        // NOTE: single barrier per step is sufficient with double buffering:
        // next iteration's STS targets the other buffer; the barrier above
        // separates this buffer's writes from the previous reads.
    }

    // ---- final term: z_f = lv[0] + sum_l lv[l] * tensors[n,n,l,0,f] ----
    const float* Wp = Tn + (size_t)n * TILE;
    float z0 = lv[0], z1 = lv[0];
#pragma unroll
    for (int l = 0; l < 16; ++l) {
        float a  = lv[l];
        float w0 = __ldg(Wp + l * 32 + 0);
        float w1 = __ldg(Wp + l * 32 + 1);
        z0 = fmaf(a, w0, z0);
        z1 = fmaf(a, w1, z1);
    }
    float mx  = fmaxf(z0, z1);
    float lse = mx + logf(expf(z0 - mx) + expf(z1 - mx));
    int   fn  = (fb[n >> 5] >> (n & 31)) & 1;
    float zf  = fn ? z1 : z0;
    g_terms[n * BSZ + b] = zf - lse;
}

// ---------------------------------------------------------------------------
// Reduce: fixed-order deterministic sum of 256 terms per sample.
// Also computes the n=0 term (log_softmax of tensors[0,0,0,0,:] + 1).
// ---------------------------------------------------------------------------
__global__ void reduce_kernel(const float* __restrict__ T, float* __restrict__ out) {
    int b = blockIdx.x * blockDim.x + threadIdx.x;   // 0..511
    if (b >= BSZ) return;

    float z0 = T[0] + 1.0f;
    float z1 = T[1] + 1.0f;
    float mx  = fmaxf(z0, z1);
    float lse = mx + logf(expf(z0 - mx) + expf(z1 - mx));
    int   f0  = g_fbits[b * 8] & 1;
    float s   = (f0 ? z1 : z0) - lse;

#pragma unroll 8
    for (int n = 1; n < NN; ++n)
        s += g_terms[n * BSZ + b];

    out[b] = s;
}

// ---------------------------------------------------------------------------
extern "C" void kernel_launch(void* const* d_in, const int* in_sizes, int n_in,
                              void* d_out, int out_size) {
    const float*     T;
    const long long* data;
    // identify inputs by element count (data: 512*256 int64, tensors: 33.5M fp32)
    if (in_sizes[0] == BSZ * NN) {
        data = (const long long*)d_in[0];
        T    = (const float*)d_in[1];
    } else {
        data = (const long long*)d_in[1];
        T    = (const float*)d_in[0];
    }

    pack_kernel<<<32, 128>>>(data);
    chain_kernel<<<255 * NQ, TPB>>>(T);
    reduce_kernel<<<4, 128>>>(T, (float*)d_out);
}